// round 7
// baseline (speedup 1.0000x reference)
#include <cuda_runtime.h>
#include <cuda_bf16.h>
#include <math.h>
#include <stdint.h>

// Problem constants
#define Bb 2
#define Ss 4096
#define INs 2048
#define STATEs 2048
#define OUTs 2048
#define Hh 16
#define Dd 128
#define CHs 6144               // 3*STATE
#define FACTOR_ 0.0214373219f  // 1/sqrt(2048+128)

// ---------------- scratch (device globals: allocation-free) ----------------
__device__ float g_z [(size_t)Bb * Ss * CHs];    // after GEMM1+tanh
__device__ float g_zc[(size_t)Bb * Ss * CHs];    // after conv

// bf16 hi/lo split buffers
__device__ __nv_bfloat16 g_xhi[(size_t)Bb * Ss * INs];
__device__ __nv_bfloat16 g_xlo[(size_t)Bb * Ss * INs];
__device__ __nv_bfloat16 g_whi[(size_t)CHs * INs];
__device__ __nv_bfloat16 g_wlo[(size_t)CHs * INs];
__device__ __nv_bfloat16 g_yhi[(size_t)Bb * Ss * STATEs];
__device__ __nv_bfloat16 g_ylo[(size_t)Bb * Ss * STATEs];
__device__ __nv_bfloat16 g_ohi[(size_t)OUTs * STATEs];
__device__ __nv_bfloat16 g_olo[(size_t)OUTs * STATEs];

// ---------------- math helpers ----------------
__device__ __forceinline__ float fast_tanh(float x) {
    float e = __expf(2.0f * x);
    return 1.0f - 2.0f / (e + 1.0f);
}
__device__ __forceinline__ float fast_sigmoid(float x) {
    return 1.0f / (1.0f + __expf(-x));
}

__device__ __forceinline__ uint32_t smem_to_u32(const void* p) {
    uint32_t a;
    asm("{ .reg .u64 t; cvta.to.shared.u64 t, %1; cvt.u32.u64 %0, t; }"
        : "=r"(a) : "l"(p));
    return a;
}
__device__ __forceinline__ void cpa16(uint32_t s, const void* g) {
    asm volatile("cp.async.cg.shared.global [%0], [%1], 16;\n"
                 :: "r"(s), "l"(g) : "memory");
}
__device__ __forceinline__ void cpa_commit() {
    asm volatile("cp.async.commit_group;\n" ::: "memory");
}
template <int N>
__device__ __forceinline__ void cpa_wait() {
    asm volatile("cp.async.wait_group %0;\n" :: "n"(N) : "memory");
}
__device__ __forceinline__ void ldsm_x4(uint32_t* r, uint32_t addr) {
    asm volatile("ldmatrix.sync.aligned.m8n8.x4.shared.b16 {%0,%1,%2,%3}, [%4];"
                 : "=r"(r[0]), "=r"(r[1]), "=r"(r[2]), "=r"(r[3]) : "r"(addr));
}
__device__ __forceinline__ void mma_bf16(float* c, const uint32_t* a, const uint32_t* b) {
    asm volatile(
        "mma.sync.aligned.m16n8k16.row.col.f32.bf16.bf16.f32 "
        "{%0,%1,%2,%3}, {%4,%5,%6,%7}, {%8,%9}, {%0,%1,%2,%3};"
        : "+f"(c[0]), "+f"(c[1]), "+f"(c[2]), "+f"(c[3])
        : "r"(a[0]), "r"(a[1]), "r"(a[2]), "r"(a[3]), "r"(b[0]), "r"(b[1]));
}

// packed f32x2 helpers (sm_100+ PTX, not 'a'-gated)
__device__ __forceinline__ unsigned long long pack2(float x, float y) {
    unsigned long long r;
    asm("mov.b64 %0, {%1, %2};" : "=l"(r) : "f"(x), "f"(y));
    return r;
}
__device__ __forceinline__ float2 unpack2(unsigned long long v) {
    float2 r;
    asm("mov.b64 {%0, %1}, %2;" : "=f"(r.x), "=f"(r.y) : "l"(v));
    return r;
}
#define FMA2(acc, a, b) \
    asm("fma.rn.f32x2 %0, %1, %2, %0;" : "+l"(acc) : "l"(a), "l"(b))
#define ADD2(r, a, b) \
    asm("add.rn.f32x2 %0, %1, %2;" : "=l"(r) : "l"(a), "l"(b))

// ---------------- split fp32 -> bf16 hi + lo --------------------------------
__global__ void __launch_bounds__(256)
split_bf16(const float* __restrict__ in, __nv_bfloat16* __restrict__ hi,
           __nv_bfloat16* __restrict__ lo, size_t n)
{
    size_t i = ((size_t)blockIdx.x * 256 + threadIdx.x) * 4;
    if (i >= n) return;
    float4 v = *(const float4*)(in + i);
    __nv_bfloat16 h0 = __float2bfloat16(v.x);
    __nv_bfloat16 h1 = __float2bfloat16(v.y);
    __nv_bfloat16 h2 = __float2bfloat16(v.z);
    __nv_bfloat16 h3 = __float2bfloat16(v.w);
    __nv_bfloat16 l0 = __float2bfloat16(v.x - __bfloat162float(h0));
    __nv_bfloat16 l1 = __float2bfloat16(v.y - __bfloat162float(h1));
    __nv_bfloat16 l2 = __float2bfloat16(v.z - __bfloat162float(h2));
    __nv_bfloat16 l3 = __float2bfloat16(v.w - __bfloat162float(h3));
    __nv_bfloat162* H = (__nv_bfloat162*)(hi + i);
    __nv_bfloat162* L = (__nv_bfloat162*)(lo + i);
    H[0] = __nv_bfloat162(h0, h1); H[1] = __nv_bfloat162(h2, h3);
    L[0] = __nv_bfloat162(l0, l1); L[1] = __nv_bfloat162(l2, l3);
}

// ---------------- HMMA GEMM: C = A * B^T (+bias)(tanh), split-bf16 ---------
// 128x128 CTA tile, 8 warps (2x4), each warp 64x32. K-chunk = 64.
// 3-stage cp.async pipeline + intra-chunk fragment double-buffering.
#define LDPB 144                     // padded row length in bytes (64 bf16 + pad)
#define ARR_BYTES (128 * LDPB)       // 18432
#define STG_BYTES (4 * ARR_BYTES)    // 73728
#define GEMM_SMEM (3 * STG_BYTES)    // 221184

template<bool TANH, bool BIAS>
__global__ void __launch_bounds__(256)
mma_gemm(const __nv_bfloat16* __restrict__ Ahi, const __nv_bfloat16* __restrict__ Alo,
         const __nv_bfloat16* __restrict__ Bhi, const __nv_bfloat16* __restrict__ Blo,
         const float* __restrict__ bias, float* __restrict__ C,
         int M, int N, int K)
{
    extern __shared__ char smem[];
    const uint32_t su = smem_to_u32(smem);
    const int tid  = threadIdx.x;
    const int wid  = tid >> 5;
    const int lane = tid & 31;
    const int bm   = blockIdx.y << 7;
    const int bn   = blockIdx.x << 7;
    const int warp_m = wid >> 2;    // 0..1
    const int warp_n = wid & 3;     // 0..3

    const int NCH = K >> 6;         // 64-wide K chunks

    auto load_chunk = [&](int ci, int st) {
        uint32_t sb = su + (uint32_t)st * STG_BYTES;
        size_t kbase = (size_t)ci * 64;
#pragma unroll
        for (int t = 0; t < 4; t++) {
            int s   = tid + t * 256;
            int row = s >> 3;
            int ks  = s & 7;
            uint32_t so = (uint32_t)row * LDPB + (uint32_t)ks * 16;
            size_t gA = (size_t)(bm + row) * K + kbase + ks * 8;
            size_t gB = (size_t)(bn + row) * K + kbase + ks * 8;
            cpa16(sb +                 so, Ahi + gA);
            cpa16(sb + 1 * ARR_BYTES + so, Alo + gA);
            cpa16(sb + 2 * ARR_BYTES + so, Bhi + gB);
            cpa16(sb + 3 * ARR_BYTES + so, Blo + gB);
        }
        cpa_commit();
    };

    float acc[4][4][4];
#pragma unroll
    for (int i = 0; i < 4; i++)
#pragma unroll
        for (int j = 0; j < 4; j++)
#pragma unroll
            for (int k = 0; k < 4; k++) acc[i][j][k] = 0.0f;

    const uint32_t a_lane = (uint32_t)((lane & 15) * LDPB + (lane >> 4) * 16)
                          + (uint32_t)(warp_m * 64) * LDPB;
    const int g = lane >> 3;
    const uint32_t b_lane = (uint32_t)((((g >> 1) * 8) + (lane & 7)) * LDPB + (g & 1) * 16)
                          + (uint32_t)(warp_n * 32) * LDPB;

    load_chunk(0, 0);
    load_chunk(1, 1);

    // fragment double buffers
    uint32_t fa_h[2][4][4], fa_l[2][4][4], fb_h[2][4][2], fb_l[2][4][2];

    for (int i = 0; i < NCH; i++) {
        if (i + 1 < NCH) cpa_wait<1>(); else cpa_wait<0>();
        __syncthreads();
        if (i + 2 < NCH) load_chunk(i + 2, (i + 2) % 3);

        uint32_t sb  = su + (uint32_t)(i % 3) * STG_BYTES;
        uint32_t ah  = sb + a_lane;
        uint32_t al  = sb + 1 * ARR_BYTES + a_lane;
        uint32_t bh  = sb + 2 * ARR_BYTES + b_lane;
        uint32_t bl  = sb + 3 * ARR_BYTES + b_lane;

        auto load_frags = [&](int ks, int buf) {
            uint32_t ko = (uint32_t)ks * 32;
#pragma unroll
            for (int mi = 0; mi < 4; mi++) {
                ldsm_x4(fa_h[buf][mi], ah + (uint32_t)(mi * 16) * LDPB + ko);
                ldsm_x4(fa_l[buf][mi], al + (uint32_t)(mi * 16) * LDPB + ko);
            }
#pragma unroll
            for (int p = 0; p < 2; p++) {
                uint32_t r[4];
                ldsm_x4(r, bh + (uint32_t)(p * 16) * LDPB + ko);
                fb_h[buf][p * 2 + 0][0] = r[0]; fb_h[buf][p * 2 + 0][1] = r[1];
                fb_h[buf][p * 2 + 1][0] = r[2]; fb_h[buf][p * 2 + 1][1] = r[3];
                ldsm_x4(r, bl + (uint32_t)(p * 16) * LDPB + ko);
                fb_l[buf][p * 2 + 0][0] = r[0]; fb_l[buf][p * 2 + 0][1] = r[1];
                fb_l[buf][p * 2 + 1][0] = r[2]; fb_l[buf][p * 2 + 1][1] = r[3];
            }
        };

        load_frags(0, 0);
#pragma unroll
        for (int ks = 0; ks < 4; ks++) {
            int cur = ks & 1;
            if (ks < 3) load_frags(ks + 1, cur ^ 1);
#pragma unroll
            for (int mi = 0; mi < 4; mi++)
#pragma unroll
                for (int ni = 0; ni < 4; ni++) {
                    mma_bf16(acc[mi][ni], fa_h[cur][mi], fb_h[cur][ni]);
                    mma_bf16(acc[mi][ni], fa_h[cur][mi], fb_l[cur][ni]);
                    mma_bf16(acc[mi][ni], fa_l[cur][mi], fb_h[cur][ni]);
                }
        }
    }

    // ---- epilogue
    const int gid = lane >> 2;
    const int tig = lane & 3;
#pragma unroll
    for (int mi = 0; mi < 4; mi++) {
        int row0 = bm + warp_m * 64 + mi * 16 + gid;
#pragma unroll
        for (int ni = 0; ni < 4; ni++) {
            int col = bn + warp_n * 32 + ni * 8 + tig * 2;
            float b0 = 0.f, b1 = 0.f;
            if (BIAS) { b0 = bias[col]; b1 = bias[col + 1]; }
            float v0 = acc[mi][ni][0] + b0;
            float v1 = acc[mi][ni][1] + b1;
            float v2 = acc[mi][ni][2] + b0;
            float v3 = acc[mi][ni][3] + b1;
            if (TANH) {
                v0 = fast_tanh(v0); v1 = fast_tanh(v1);
                v2 = fast_tanh(v2); v3 = fast_tanh(v3);
            }
            *(float2*)(C + (size_t)row0 * N + col)       = make_float2(v0, v1);
            *(float2*)(C + (size_t)(row0 + 8) * N + col) = make_float2(v2, v3);
        }
    }
}

// ---------------- depthwise causal conv (K=4) + bias, * FACTOR -------------
__global__ void __launch_bounds__(256)
gru_conv(const float* __restrict__ z, const float* __restrict__ cw,
         const float* __restrict__ cb, float* __restrict__ out)
{
    const int c  = blockIdx.x * 256 + threadIdx.x;
    const int s0 = blockIdx.y * 256;
    const int b  = blockIdx.z;

    const float w0 = cw[c * 4 + 0];
    const float w1 = cw[c * 4 + 1];
    const float w2 = cw[c * 4 + 2];
    const float w3 = cw[c * 4 + 3];
    const float bi = cb[c];

    const float* zp = z   + (size_t)b * Ss * CHs + c;
    float*       op = out + (size_t)b * Ss * CHs + c;

    float x0 = (s0 >= 3) ? zp[(size_t)(s0 - 3) * CHs] : 0.0f;
    float x1 = (s0 >= 2) ? zp[(size_t)(s0 - 2) * CHs] : 0.0f;
    float x2 = (s0 >= 1) ? zp[(size_t)(s0 - 1) * CHs] : 0.0f;

    for (int s = s0; s < s0 + 256; s++) {
        float x3 = zp[(size_t)s * CHs];
        float r  = w0 * x0 + w1 * x1 + w2 * x2 + w3 * x3;
        op[(size_t)s * CHs] = (r + bi) * FACTOR_;
        x0 = x1; x1 = x2; x2 = x3;
    }
}

// ---------------- GRU scan v4: shfl-quad reduction, 2 barriers/step --------
// grid = 32 (b,h). 256 threads. Thread = (c2 = tid>>2, q = tid&3):
// columns (2c2, 2c2+1), d-range [32q, 32q+32). The 4 q-partners of a column
// pair are lanes 4c2..4c2+3 of the SAME warp -> cross-quarter reduction via
// 2 shfl.bfly rounds (no smem partials, no extra barriers).
// Quad-lane-0 (q==0) finalizes gates (64 finalizers, spread over all warps).
__global__ void __launch_bounds__(256, 1)
gru_scan2(const float* __restrict__ zc, const float* __restrict__ sw,
          __nv_bfloat16* __restrict__ yh, __nv_bfloat16* __restrict__ yl)
{
    __shared__ __align__(16) unsigned long long h_pair[128];   // (h,h)
    __shared__ __align__(16) unsigned long long rh_pair[128];  // (r*h, r*h)

    const int tid = threadIdx.x;
    const int b   = blockIdx.x >> 4;
    const int hh  = blockIdx.x & 15;
    const int c2  = tid >> 2;      // 0..63 column pair
    const int q   = tid & 3;       // d-quarter
    const int d0  = q << 5;

    const float* wc_g = sw + (size_t)(hh)      * Dd * Dd;  // cand
    const float* wf_g = sw + (size_t)(16 + hh) * Dd * Dd;  // forget
    const float* wr_g = sw + (size_t)(32 + hh) * Dd * Dd;  // reset

    unsigned long long wc[32], wf[32], wr[32];
#pragma unroll
    for (int j = 0; j < 32; j++) {
        float2 t;
        t = *(const float2*)(wc_g + (size_t)(d0 + j) * 128 + 2 * c2);
        wc[j] = pack2(t.x * FACTOR_, t.y * FACTOR_);
        t = *(const float2*)(wf_g + (size_t)(d0 + j) * 128 + 2 * c2);
        wf[j] = pack2(t.x * FACTOR_, t.y * FACTOR_);
        t = *(const float2*)(wr_g + (size_t)(d0 + j) * 128 + 2 * c2);
        wr[j] = pack2(t.x * FACTOR_, t.y * FACTOR_);
    }
    if (tid < 128) h_pair[tid] = 0ULL;
    __syncthreads();

    const float* zb = zc + (size_t)b * Ss * CHs + hh * 128 + 2 * c2;
    __nv_bfloat16* yhb = yh + (size_t)b * Ss * STATEs + hh * 128 + 2 * c2;
    __nv_bfloat16* ylb = yl + (size_t)b * Ss * STATEs + hh * 128 + 2 * c2;

    float2 iin = make_float2(0.f, 0.f);
    float2 fin2 = make_float2(0.f, 0.f);
    float2 rin = make_float2(0.f, 0.f);
    if (q == 0) {
        iin  = *(const float2*)(zb);
        fin2 = *(const float2*)(zb + 2048);
        rin  = *(const float2*)(zb + 4096);
    }
    float h0 = 0.f, h1 = 0.f, f0 = 0.f, f1 = 0.f;

    for (int s = 0; s < Ss; s++) {
        float2 ni = make_float2(0.f, 0.f);
        float2 nf = make_float2(0.f, 0.f);
        float2 nr = make_float2(0.f, 0.f);
        if (q == 0 && s + 1 < Ss) {
            const float* zs = zb + (size_t)(s + 1) * CHs;
            ni = *(const float2*)(zs);
            nf = *(const float2*)(zs + 2048);
            nr = *(const float2*)(zs + 4096);
        }

        // phase 1: partial r/f over d in [d0, d0+32)
        unsigned long long ar0 = 0ULL, ar1 = 0ULL, af0 = 0ULL, af1 = 0ULL;
        {
            const ulonglong2* hp = (const ulonglong2*)(h_pair + d0);
#pragma unroll
            for (int j = 0; j < 16; j++) {
                ulonglong2 hv = hp[j];
                FMA2(ar0, hv.x, wr[2 * j]);
                FMA2(af0, hv.x, wf[2 * j]);
                FMA2(ar1, hv.y, wr[2 * j + 1]);
                FMA2(af1, hv.y, wf[2 * j + 1]);
            }
        }
        unsigned long long ar, af, t;
        ADD2(ar, ar0, ar1);
        ADD2(af, af0, af1);
        t = __shfl_xor_sync(0xffffffffu, ar, 1); ADD2(ar, ar, t);
        t = __shfl_xor_sync(0xffffffffu, af, 1); ADD2(af, af, t);
        t = __shfl_xor_sync(0xffffffffu, ar, 2); ADD2(ar, ar, t);
        t = __shfl_xor_sync(0xffffffffu, af, 2); ADD2(af, af, t);

        if (q == 0) {
            float2 rv = unpack2(ar), fv = unpack2(af);
            float r0 = fast_sigmoid(rin.x + rv.x);
            float r1 = fast_sigmoid(rin.y + rv.y);
            f0 = fast_sigmoid(fin2.x + fv.x);
            f1 = fast_sigmoid(fin2.y + fv.y);
            float rh0 = r0 * h0, rh1 = r1 * h1;
            rh_pair[2 * c2]     = pack2(rh0, rh0);
            rh_pair[2 * c2 + 1] = pack2(rh1, rh1);
        }
        __syncthreads();

        // phase 2: partial cand on (r*h)
        unsigned long long ac0 = 0ULL, ac1 = 0ULL;
        {
            const ulonglong2* rp = (const ulonglong2*)(rh_pair + d0);
#pragma unroll
            for (int j = 0; j < 16; j++) {
                ulonglong2 hv = rp[j];
                FMA2(ac0, hv.x, wc[2 * j]);
                FMA2(ac1, hv.y, wc[2 * j + 1]);
            }
        }
        unsigned long long ac;
        ADD2(ac, ac0, ac1);
        t = __shfl_xor_sync(0xffffffffu, ac, 1); ADD2(ac, ac, t);
        t = __shfl_xor_sync(0xffffffffu, ac, 2); ADD2(ac, ac, t);

        if (q == 0) {
            float2 cv = unpack2(ac);
            float c0 = fast_tanh(iin.x + cv.x);
            float c1 = fast_tanh(iin.y + cv.y);
            float hn0 = fmaf(f0, h0 - c0, c0);   // f*h + (1-f)*cand
            float hn1 = fmaf(f1, h1 - c1, c1);
            h0 = hn0; h1 = hn1;
            h_pair[2 * c2]     = pack2(hn0, hn0);
            h_pair[2 * c2 + 1] = pack2(hn1, hn1);
            __nv_bfloat16 b0 = __float2bfloat16(hn0);
            __nv_bfloat16 b1 = __float2bfloat16(hn1);
            *(__nv_bfloat162*)(yhb + (size_t)s * STATEs) = __nv_bfloat162(b0, b1);
            *(__nv_bfloat162*)(ylb + (size_t)s * STATEs) =
                __nv_bfloat162(__float2bfloat16(hn0 - __bfloat162float(b0)),
                               __float2bfloat16(hn1 - __bfloat162float(b1)));
            iin = ni; fin2 = nf; rin = nr;
        }
        __syncthreads();
    }
}

// ---------------- launch ----------------
extern "C" void kernel_launch(void* const* d_in, const int* in_sizes, int n_in,
                              void* d_out, int out_size)
{
    const float* x    = (const float*)d_in[0];
    const float* w_in = (const float*)d_in[1];
    const float* b_in = (const float*)d_in[2];
    const float* cw   = (const float*)d_in[3];
    const float* cb   = (const float*)d_in[4];
    const float* swt  = (const float*)d_in[5];
    const float* wout = (const float*)d_in[6];
    float* out = (float*)d_out;

    float *zp, *zcp;
    cudaGetSymbolAddress((void**)&zp,  g_z);
    cudaGetSymbolAddress((void**)&zcp, g_zc);
    __nv_bfloat16 *xh, *xl, *wh, *wl, *yh, *yl, *oh, *ol;
    cudaGetSymbolAddress((void**)&xh, g_xhi);
    cudaGetSymbolAddress((void**)&xl, g_xlo);
    cudaGetSymbolAddress((void**)&wh, g_whi);
    cudaGetSymbolAddress((void**)&wl, g_wlo);
    cudaGetSymbolAddress((void**)&yh, g_yhi);
    cudaGetSymbolAddress((void**)&yl, g_ylo);
    cudaGetSymbolAddress((void**)&oh, g_ohi);
    cudaGetSymbolAddress((void**)&ol, g_olo);

    // split inputs to bf16 hi/lo
    {
        size_t nx = (size_t)Bb * Ss * INs;
        split_bf16<<<(int)(nx / 1024), 256>>>(x, xh, xl, nx);
        size_t nw = (size_t)CHs * INs;
        split_bf16<<<(int)(nw / 1024), 256>>>(w_in, wh, wl, nw);
        size_t no = (size_t)OUTs * STATEs;
        split_bf16<<<(int)(no / 1024), 256>>>(wout, oh, ol, no);
    }

    // GEMM1 (HMMA, 3-stage + frag double-buffer): z = tanh(x @ w_in^T + b_in)
    {
        cudaFuncSetAttribute(mma_gemm<true, true>,
                             cudaFuncAttributeMaxDynamicSharedMemorySize,
                             GEMM_SMEM);
        dim3 grid(CHs / 128, (Bb * Ss) / 128);
        mma_gemm<true, true><<<grid, 256, GEMM_SMEM>>>(
            xh, xl, wh, wl, b_in, zp, Bb * Ss, CHs, INs);
    }
    // conv
    {
        dim3 grid(CHs / 256, Ss / 256, Bb);
        gru_conv<<<grid, 256>>>(zp, cw, cb, zcp);
    }
    // scan v4 (emits yh/yl directly)
    {
        gru_scan2<<<Bb * Hh, 256>>>(zcp, swt, yh, yl);
    }
    // GEMM2 (HMMA): out = y @ w_out^T
    {
        cudaFuncSetAttribute(mma_gemm<false, false>,
                             cudaFuncAttributeMaxDynamicSharedMemorySize,
                             GEMM_SMEM);
        dim3 grid(OUTs / 128, (Bb * Ss) / 128);
        mma_gemm<false, false><<<grid, 256, GEMM_SMEM>>>(
            yh, yl, oh, ol, (const float*)0, out, Bb * Ss, OUTs, STATEs);
    }
}

// round 8
// speedup vs baseline: 2.5333x; 2.5333x over previous
#include <cuda_runtime.h>
#include <cuda_bf16.h>
#include <math.h>
#include <stdint.h>

// Problem constants
#define Bb 2
#define Ss 4096
#define INs 2048
#define STATEs 2048
#define OUTs 2048
#define Hh 16
#define Dd 128
#define CHs 6144               // 3*STATE
#define FACTOR_ 0.0214373219f  // 1/sqrt(2048+128)

// ---------------- scratch (device globals: allocation-free) ----------------
__device__ float g_z [(size_t)Bb * Ss * CHs];    // after GEMM1+tanh
__device__ float g_zc[(size_t)Bb * Ss * CHs];    // after conv

// bf16 hi/lo split buffers
__device__ __nv_bfloat16 g_xhi[(size_t)Bb * Ss * INs];
__device__ __nv_bfloat16 g_xlo[(size_t)Bb * Ss * INs];
__device__ __nv_bfloat16 g_whi[(size_t)CHs * INs];
__device__ __nv_bfloat16 g_wlo[(size_t)CHs * INs];
__device__ __nv_bfloat16 g_yhi[(size_t)Bb * Ss * STATEs];
__device__ __nv_bfloat16 g_ylo[(size_t)Bb * Ss * STATEs];
__device__ __nv_bfloat16 g_ohi[(size_t)OUTs * STATEs];
__device__ __nv_bfloat16 g_olo[(size_t)OUTs * STATEs];

// ---------------- math helpers ----------------
__device__ __forceinline__ float fast_tanh(float x) {
    float e = __expf(2.0f * x);
    return 1.0f - 2.0f / (e + 1.0f);
}
__device__ __forceinline__ float fast_sigmoid(float x) {
    return 1.0f / (1.0f + __expf(-x));
}

__device__ __forceinline__ uint32_t smem_to_u32(const void* p) {
    uint32_t a;
    asm("{ .reg .u64 t; cvta.to.shared.u64 t, %1; cvt.u32.u64 %0, t; }"
        : "=r"(a) : "l"(p));
    return a;
}
__device__ __forceinline__ void cpa16(uint32_t s, const void* g) {
    asm volatile("cp.async.cg.shared.global [%0], [%1], 16;\n"
                 :: "r"(s), "l"(g) : "memory");
}
__device__ __forceinline__ void cpa_commit() {
    asm volatile("cp.async.commit_group;\n" ::: "memory");
}
template <int N>
__device__ __forceinline__ void cpa_wait() {
    asm volatile("cp.async.wait_group %0;\n" :: "n"(N) : "memory");
}
__device__ __forceinline__ void ldsm_x4(uint32_t* r, uint32_t addr) {
    asm volatile("ldmatrix.sync.aligned.m8n8.x4.shared.b16 {%0,%1,%2,%3}, [%4];"
                 : "=r"(r[0]), "=r"(r[1]), "=r"(r[2]), "=r"(r[3]) : "r"(addr));
}
__device__ __forceinline__ void mma_bf16(float* c, const uint32_t* a, const uint32_t* b) {
    asm volatile(
        "mma.sync.aligned.m16n8k16.row.col.f32.bf16.bf16.f32 "
        "{%0,%1,%2,%3}, {%4,%5,%6,%7}, {%8,%9}, {%0,%1,%2,%3};"
        : "+f"(c[0]), "+f"(c[1]), "+f"(c[2]), "+f"(c[3])
        : "r"(a[0]), "r"(a[1]), "r"(a[2]), "r"(a[3]), "r"(b[0]), "r"(b[1]));
}

// packed f32x2 helpers (sm_100+ PTX, not 'a'-gated)
__device__ __forceinline__ unsigned long long pack2(float x, float y) {
    unsigned long long r;
    asm("mov.b64 %0, {%1, %2};" : "=l"(r) : "f"(x), "f"(y));
    return r;
}
#define FMA2(acc, a, b) \
    asm("fma.rn.f32x2 %0, %1, %2, %0;" : "+l"(acc) : "l"(a), "l"(b))
#define ADD2(r, a, b) \
    asm("add.rn.f32x2 %0, %1, %2;" : "=l"(r) : "l"(a), "l"(b))

// ---------------- split fp32 -> bf16 hi + lo --------------------------------
__global__ void __launch_bounds__(256)
split_bf16(const float* __restrict__ in, __nv_bfloat16* __restrict__ hi,
           __nv_bfloat16* __restrict__ lo, size_t n)
{
    size_t i = ((size_t)blockIdx.x * 256 + threadIdx.x) * 4;
    if (i >= n) return;
    float4 v = *(const float4*)(in + i);
    __nv_bfloat16 h0 = __float2bfloat16(v.x);
    __nv_bfloat16 h1 = __float2bfloat16(v.y);
    __nv_bfloat16 h2 = __float2bfloat16(v.z);
    __nv_bfloat16 h3 = __float2bfloat16(v.w);
    __nv_bfloat16 l0 = __float2bfloat16(v.x - __bfloat162float(h0));
    __nv_bfloat16 l1 = __float2bfloat16(v.y - __bfloat162float(h1));
    __nv_bfloat16 l2 = __float2bfloat16(v.z - __bfloat162float(h2));
    __nv_bfloat16 l3 = __float2bfloat16(v.w - __bfloat162float(h3));
    __nv_bfloat162* H = (__nv_bfloat162*)(hi + i);
    __nv_bfloat162* L = (__nv_bfloat162*)(lo + i);
    H[0] = __nv_bfloat162(h0, h1); H[1] = __nv_bfloat162(h2, h3);
    L[0] = __nv_bfloat162(l0, l1); L[1] = __nv_bfloat162(l2, l3);
}

// ---------------- HMMA GEMM: C = A * B^T (+bias)(tanh), split-bf16 ---------
// 256x128 CTA tile, 16 warps (4x4), each warp 64x32 (same warp tile as R6).
// K-chunk = 64, 2-stage cp.async pipeline.
#define LDPB 144                     // padded row length in bytes (64 bf16 + pad)
#define A_ROWS 256
#define B_ROWS 128
#define A_BYTES (A_ROWS * LDPB)      // 36864
#define B_BYTES (B_ROWS * LDPB)      // 18432
#define STG_BYTES (2 * A_BYTES + 2 * B_BYTES)  // 110592
#define GEMM_SMEM (2 * STG_BYTES)    // 221184

template<bool TANH, bool BIAS>
__global__ void __launch_bounds__(512)
mma_gemm(const __nv_bfloat16* __restrict__ Ahi, const __nv_bfloat16* __restrict__ Alo,
         const __nv_bfloat16* __restrict__ Bhi, const __nv_bfloat16* __restrict__ Blo,
         const float* __restrict__ bias, float* __restrict__ C,
         int M, int N, int K)
{
    extern __shared__ char smem[];
    const uint32_t su = smem_to_u32(smem);
    const int tid  = threadIdx.x;
    const int wid  = tid >> 5;
    const int lane = tid & 31;
    const int bm   = blockIdx.y << 8;   // 256-row tiles
    const int bn   = blockIdx.x << 7;   // 128-col tiles
    const int warp_m = wid >> 2;    // 0..3
    const int warp_n = wid & 3;     // 0..3

    const int NCH = K >> 6;         // 64-wide K chunks

    auto load_chunk = [&](int ci, int st) {
        uint32_t sb = su + (uint32_t)st * STG_BYTES;
        size_t kbase = (size_t)ci * 64;
        // A arrays: 256 rows x 8 segs = 2048 segs, 4 per thread
#pragma unroll
        for (int t = 0; t < 4; t++) {
            int s   = tid + t * 512;
            int row = s >> 3;
            int ks  = s & 7;
            uint32_t so = (uint32_t)row * LDPB + (uint32_t)ks * 16;
            size_t gA = (size_t)(bm + row) * K + kbase + ks * 8;
            cpa16(sb +           so, Ahi + gA);
            cpa16(sb + A_BYTES + so, Alo + gA);
        }
        // B arrays: 128 rows x 8 segs = 1024 segs, 2 per thread
#pragma unroll
        for (int t = 0; t < 2; t++) {
            int s   = tid + t * 512;
            int row = s >> 3;
            int ks  = s & 7;
            uint32_t so = (uint32_t)row * LDPB + (uint32_t)ks * 16;
            size_t gB = (size_t)(bn + row) * K + kbase + ks * 8;
            cpa16(sb + 2 * A_BYTES +           so, Bhi + gB);
            cpa16(sb + 2 * A_BYTES + B_BYTES + so, Blo + gB);
        }
        cpa_commit();
    };

    float acc[4][4][4];
#pragma unroll
    for (int i = 0; i < 4; i++)
#pragma unroll
        for (int j = 0; j < 4; j++)
#pragma unroll
            for (int k = 0; k < 4; k++) acc[i][j][k] = 0.0f;

    const uint32_t a_lane = (uint32_t)((lane & 15) * LDPB + (lane >> 4) * 16)
                          + (uint32_t)(warp_m * 64) * LDPB;
    const int g = lane >> 3;
    const uint32_t b_lane = (uint32_t)((((g >> 1) * 8) + (lane & 7)) * LDPB + (g & 1) * 16)
                          + (uint32_t)(warp_n * 32) * LDPB;

    load_chunk(0, 0);

    for (int i = 0; i < NCH; i++) {
        __syncthreads();                       // stage being overwritten is free
        if (i + 1 < NCH) load_chunk(i + 1, (i + 1) & 1);
        if (i + 1 < NCH) cpa_wait<1>(); else cpa_wait<0>();
        __syncthreads();                       // chunk i resident for all

        uint32_t sb  = su + (uint32_t)(i & 1) * STG_BYTES;
        uint32_t ah  = sb + a_lane;
        uint32_t al  = sb + A_BYTES + a_lane;
        uint32_t bh  = sb + 2 * A_BYTES + b_lane;
        uint32_t bl  = sb + 2 * A_BYTES + B_BYTES + b_lane;

#pragma unroll
        for (int ks = 0; ks < 4; ks++) {
            uint32_t ko = (uint32_t)ks * 32;   // 16 bf16 = 32 bytes
            uint32_t fa_h[4][4], fa_l[4][4];
            uint32_t fb_h[4][2], fb_l[4][2];
#pragma unroll
            for (int mi = 0; mi < 4; mi++) {
                ldsm_x4(fa_h[mi], ah + (uint32_t)(mi * 16) * LDPB + ko);
                ldsm_x4(fa_l[mi], al + (uint32_t)(mi * 16) * LDPB + ko);
            }
#pragma unroll
            for (int p = 0; p < 2; p++) {
                uint32_t r[4];
                ldsm_x4(r, bh + (uint32_t)(p * 16) * LDPB + ko);
                fb_h[p * 2 + 0][0] = r[0]; fb_h[p * 2 + 0][1] = r[1];
                fb_h[p * 2 + 1][0] = r[2]; fb_h[p * 2 + 1][1] = r[3];
                ldsm_x4(r, bl + (uint32_t)(p * 16) * LDPB + ko);
                fb_l[p * 2 + 0][0] = r[0]; fb_l[p * 2 + 0][1] = r[1];
                fb_l[p * 2 + 1][0] = r[2]; fb_l[p * 2 + 1][1] = r[3];
            }
#pragma unroll
            for (int mi = 0; mi < 4; mi++)
#pragma unroll
                for (int ni = 0; ni < 4; ni++) {
                    mma_bf16(acc[mi][ni], fa_h[mi], fb_h[ni]);
                    mma_bf16(acc[mi][ni], fa_h[mi], fb_l[ni]);
                    mma_bf16(acc[mi][ni], fa_l[mi], fb_h[ni]);
                }
        }
    }

    // ---- epilogue
    const int gid = lane >> 2;
    const int tig = lane & 3;
#pragma unroll
    for (int mi = 0; mi < 4; mi++) {
        int row0 = bm + warp_m * 64 + mi * 16 + gid;
#pragma unroll
        for (int ni = 0; ni < 4; ni++) {
            int col = bn + warp_n * 32 + ni * 8 + tig * 2;
            float b0 = 0.f, b1 = 0.f;
            if (BIAS) { b0 = bias[col]; b1 = bias[col + 1]; }
            float v0 = acc[mi][ni][0] + b0;
            float v1 = acc[mi][ni][1] + b1;
            float v2 = acc[mi][ni][2] + b0;
            float v3 = acc[mi][ni][3] + b1;
            if (TANH) {
                v0 = fast_tanh(v0); v1 = fast_tanh(v1);
                v2 = fast_tanh(v2); v3 = fast_tanh(v3);
            }
            *(float2*)(C + (size_t)row0 * N + col)       = make_float2(v0, v1);
            *(float2*)(C + (size_t)(row0 + 8) * N + col) = make_float2(v2, v3);
        }
    }
}

// ---------------- depthwise causal conv (K=4) + bias, * FACTOR -------------
__global__ void __launch_bounds__(256)
gru_conv(const float* __restrict__ z, const float* __restrict__ cw,
         const float* __restrict__ cb, float* __restrict__ out)
{
    const int c  = blockIdx.x * 256 + threadIdx.x;
    const int s0 = blockIdx.y * 256;
    const int b  = blockIdx.z;

    const float w0 = cw[c * 4 + 0];
    const float w1 = cw[c * 4 + 1];
    const float w2 = cw[c * 4 + 2];
    const float w3 = cw[c * 4 + 3];
    const float bi = cb[c];

    const float* zp = z   + (size_t)b * Ss * CHs + c;
    float*       op = out + (size_t)b * Ss * CHs + c;

    float x0 = (s0 >= 3) ? zp[(size_t)(s0 - 3) * CHs] : 0.0f;
    float x1 = (s0 >= 2) ? zp[(size_t)(s0 - 2) * CHs] : 0.0f;
    float x2 = (s0 >= 1) ? zp[(size_t)(s0 - 1) * CHs] : 0.0f;

    for (int s = s0; s < s0 + 256; s++) {
        float x3 = zp[(size_t)s * CHs];
        float r  = w0 * x0 + w1 * x1 + w2 * x2 + w3 * x3;
        op[(size_t)s * CHs] = (r + bi) * FACTOR_;
        x0 = x1; x1 = x2; x2 = x3;
    }
}

// ---------------- GRU scan v3 (R6, known good): register weights + f32x2 ---
// grid = 32 (b,h). 256 threads: c2 = tid&63 -> col pair (2c2, 2c2+1),
// q = tid>>6 -> d-range [32q, 32q+32). Weights in registers (192/thread).
// Finalizer = 128 threads, 1 column each. Emits yh/yl bf16 directly.
__global__ void __launch_bounds__(256, 1)
gru_scan2(const float* __restrict__ zc, const float* __restrict__ sw,
          __nv_bfloat16* __restrict__ yh, __nv_bfloat16* __restrict__ yl)
{
    __shared__ __align__(16) unsigned long long h_pair[128];   // (h,h)
    __shared__ __align__(16) unsigned long long rh_pair[128];  // (r*h, r*h)
    __shared__ float sf[128];                                  // f per column
    __shared__ unsigned long long pr[4][64], pf[4][64], pc[4][64];

    const int tid = threadIdx.x;
    const int b   = blockIdx.x >> 4;
    const int hh  = blockIdx.x & 15;
    const int c2  = tid & 63;
    const int q   = tid >> 6;
    const int d0  = q << 5;

    const float* wc_g = sw + (size_t)(hh)      * Dd * Dd;  // cand
    const float* wf_g = sw + (size_t)(16 + hh) * Dd * Dd;  // forget
    const float* wr_g = sw + (size_t)(32 + hh) * Dd * Dd;  // reset

    unsigned long long wc[32], wf[32], wr[32];
#pragma unroll
    for (int j = 0; j < 32; j++) {
        float2 t;
        t = *(const float2*)(wc_g + (size_t)(d0 + j) * 128 + 2 * c2);
        wc[j] = pack2(t.x * FACTOR_, t.y * FACTOR_);
        t = *(const float2*)(wf_g + (size_t)(d0 + j) * 128 + 2 * c2);
        wf[j] = pack2(t.x * FACTOR_, t.y * FACTOR_);
        t = *(const float2*)(wr_g + (size_t)(d0 + j) * 128 + 2 * c2);
        wr[j] = pack2(t.x * FACTOR_, t.y * FACTOR_);
    }
    if (tid < 128) h_pair[tid] = 0ULL;
    __syncthreads();

    // finalizer: one column per thread (tid < 128)
    const float* zb = zc + (size_t)b * Ss * CHs + hh * 128 + tid;
    __nv_bfloat16* yhb = yh + (size_t)b * Ss * STATEs + hh * 128 + tid;
    __nv_bfloat16* ylb = yl + (size_t)b * Ss * STATEs + hh * 128 + tid;
    const float* prf = (const float*)pr;   // [4][128] view
    const float* pff = (const float*)pf;
    const float* pcf = (const float*)pc;

    float iin = 0.f, fin = 0.f, rin = 0.f;
    if (tid < 128) {
        iin = zb[0];
        fin = zb[2048];
        rin = zb[4096];
    }
    float hcur = 0.f;

    for (int s = 0; s < Ss; s++) {
        float ni = 0.f, nf = 0.f, nr = 0.f;
        if (tid < 128 && s + 1 < Ss) {
            const float* zs = zb + (size_t)(s + 1) * CHs;
            ni = zs[0];
            nf = zs[2048];
            nr = zs[4096];
        }

        // phase 1: partial r/f over d in [d0, d0+32), 2 accums per gate
        unsigned long long ar0 = 0ULL, ar1 = 0ULL, af0 = 0ULL, af1 = 0ULL;
        {
            const ulonglong2* hp = (const ulonglong2*)(h_pair + d0);
#pragma unroll
            for (int j = 0; j < 16; j++) {
                ulonglong2 hv = hp[j];
                FMA2(ar0, hv.x, wr[2 * j]);
                FMA2(af0, hv.x, wf[2 * j]);
                FMA2(ar1, hv.y, wr[2 * j + 1]);
                FMA2(af1, hv.y, wf[2 * j + 1]);
            }
        }
        unsigned long long art, aft;
        ADD2(art, ar0, ar1);
        ADD2(aft, af0, af1);
        pr[q][c2] = art;
        pf[q][c2] = aft;
        __syncthreads();

        float ff = 0.f;
        if (tid < 128) {
            float rs = rin + prf[tid] + prf[128 + tid] + prf[256 + tid] + prf[384 + tid];
            float fs = fin + pff[tid] + pff[128 + tid] + pff[256 + tid] + pff[384 + tid];
            float r  = fast_sigmoid(rs);
            ff = fast_sigmoid(fs);
            float rh = r * hcur;
            rh_pair[tid] = pack2(rh, rh);
            sf[tid] = ff;
        }
        __syncthreads();

        // phase 2: partial cand on (r*h)
        unsigned long long ac0 = 0ULL, ac1 = 0ULL;
        {
            const ulonglong2* rp = (const ulonglong2*)(rh_pair + d0);
#pragma unroll
            for (int j = 0; j < 16; j++) {
                ulonglong2 hv = rp[j];
                FMA2(ac0, hv.x, wc[2 * j]);
                FMA2(ac1, hv.y, wc[2 * j + 1]);
            }
        }
        unsigned long long act;
        ADD2(act, ac0, ac1);
        pc[q][c2] = act;
        __syncthreads();

        if (tid < 128) {
            float cs = iin + pcf[tid] + pcf[128 + tid] + pcf[256 + tid] + pcf[384 + tid];
            float cd = fast_tanh(cs);
            float hn = fmaf(ff, hcur - cd, cd);   // f*h + (1-f)*cand
            hcur = hn;
            h_pair[tid] = pack2(hn, hn);
            __nv_bfloat16 bh = __float2bfloat16(hn);
            yhb[(size_t)s * STATEs] = bh;
            ylb[(size_t)s * STATEs] = __float2bfloat16(hn - __bfloat162float(bh));
            iin = ni; fin = nf; rin = nr;
        }
        __syncthreads();
    }
}

// ---------------- launch ----------------
extern "C" void kernel_launch(void* const* d_in, const int* in_sizes, int n_in,
                              void* d_out, int out_size)
{
    const float* x    = (const float*)d_in[0];
    const float* w_in = (const float*)d_in[1];
    const float* b_in = (const float*)d_in[2];
    const float* cw   = (const float*)d_in[3];
    const float* cb   = (const float*)d_in[4];
    const float* swt  = (const float*)d_in[5];
    const float* wout = (const float*)d_in[6];
    float* out = (float*)d_out;

    float *zp, *zcp;
    cudaGetSymbolAddress((void**)&zp,  g_z);
    cudaGetSymbolAddress((void**)&zcp, g_zc);
    __nv_bfloat16 *xh, *xl, *wh, *wl, *yh, *yl, *oh, *ol;
    cudaGetSymbolAddress((void**)&xh, g_xhi);
    cudaGetSymbolAddress((void**)&xl, g_xlo);
    cudaGetSymbolAddress((void**)&wh, g_whi);
    cudaGetSymbolAddress((void**)&wl, g_wlo);
    cudaGetSymbolAddress((void**)&yh, g_yhi);
    cudaGetSymbolAddress((void**)&yl, g_ylo);
    cudaGetSymbolAddress((void**)&oh, g_ohi);
    cudaGetSymbolAddress((void**)&ol, g_olo);

    // split inputs to bf16 hi/lo
    {
        size_t nx = (size_t)Bb * Ss * INs;
        split_bf16<<<(int)(nx / 1024), 256>>>(x, xh, xl, nx);
        size_t nw = (size_t)CHs * INs;
        split_bf16<<<(int)(nw / 1024), 256>>>(w_in, wh, wl, nw);
        size_t no = (size_t)OUTs * STATEs;
        split_bf16<<<(int)(no / 1024), 256>>>(wout, oh, ol, no);
    }

    // GEMM1 (HMMA, 256x128 tiles, 512 thr): z = tanh(x @ w_in^T + b_in)
    {
        cudaFuncSetAttribute(mma_gemm<true, true>,
                             cudaFuncAttributeMaxDynamicSharedMemorySize,
                             GEMM_SMEM);
        dim3 grid(CHs / 128, (Bb * Ss) / 256);
        mma_gemm<true, true><<<grid, 512, GEMM_SMEM>>>(
            xh, xl, wh, wl, b_in, zp, Bb * Ss, CHs, INs);
    }
    // conv
    {
        dim3 grid(CHs / 256, Ss / 256, Bb);
        gru_conv<<<grid, 256>>>(zp, cw, cb, zcp);
    }
    // scan v3 (emits yh/yl directly)
    {
        gru_scan2<<<Bb * Hh, 256>>>(zcp, swt, yh, yl);
    }
    // GEMM2 (HMMA, 256x128 tiles, 512 thr): out = y @ w_out^T
    {
        cudaFuncSetAttribute(mma_gemm<false, false>,
                             cudaFuncAttributeMaxDynamicSharedMemorySize,
                             GEMM_SMEM);
        dim3 grid(OUTs / 128, (Bb * Ss) / 256);
        mma_gemm<false, false><<<grid, 512, GEMM_SMEM>>>(
            yh, yl, oh, ol, (const float*)0, out, Bb * Ss, OUTs, STATEs);
    }
}

// round 9
// speedup vs baseline: 3.1155x; 1.2298x over previous
#include <cuda_runtime.h>
#include <cuda_bf16.h>
#include <math.h>
#include <stdint.h>

// Problem constants
#define Bb 2
#define Ss 4096
#define INs 2048
#define STATEs 2048
#define OUTs 2048
#define Hh 16
#define Dd 128
#define CHs 6144               // 3*STATE
#define FACTOR_ 0.0214373219f  // 1/sqrt(2048+128)

#define N_SCAN_CTAS 32
#define N_WORKERS   116
#define CHUNK_S     128        // s-steps per completion chunk
#define N_CHUNKS    (Ss / CHUNK_S)          // 32
#define TILES_PER_CHUNK (2 * (CHs / 128))   // 96
#define N_TILES     (N_CHUNKS * TILES_PER_CHUNK)  // 3072

// ---------------- scratch (device globals: allocation-free) ----------------
__device__ float g_z [(size_t)Bb * Ss * CHs];    // after GEMM1+tanh
__device__ int   g_done[N_CHUNKS];               // per-chunk tile counters

// bf16 hi/lo split buffers
__device__ __nv_bfloat16 g_xhi[(size_t)Bb * Ss * INs];
__device__ __nv_bfloat16 g_xlo[(size_t)Bb * Ss * INs];
__device__ __nv_bfloat16 g_whi[(size_t)CHs * INs];
__device__ __nv_bfloat16 g_wlo[(size_t)CHs * INs];
__device__ __nv_bfloat16 g_yhi[(size_t)Bb * Ss * STATEs];
__device__ __nv_bfloat16 g_ylo[(size_t)Bb * Ss * STATEs];
__device__ __nv_bfloat16 g_ohi[(size_t)OUTs * STATEs];
__device__ __nv_bfloat16 g_olo[(size_t)OUTs * STATEs];

// ---------------- math helpers ----------------
__device__ __forceinline__ float fast_tanh(float x) {
    float e = __expf(2.0f * x);
    return 1.0f - 2.0f / (e + 1.0f);
}
__device__ __forceinline__ float fast_sigmoid(float x) {
    return 1.0f / (1.0f + __expf(-x));
}

__device__ __forceinline__ uint32_t smem_to_u32(const void* p) {
    uint32_t a;
    asm("{ .reg .u64 t; cvta.to.shared.u64 t, %1; cvt.u32.u64 %0, t; }"
        : "=r"(a) : "l"(p));
    return a;
}
__device__ __forceinline__ void cpa16(uint32_t s, const void* g) {
    asm volatile("cp.async.cg.shared.global [%0], [%1], 16;\n"
                 :: "r"(s), "l"(g) : "memory");
}
__device__ __forceinline__ void cpa_commit() {
    asm volatile("cp.async.commit_group;\n" ::: "memory");
}
template <int N>
__device__ __forceinline__ void cpa_wait() {
    asm volatile("cp.async.wait_group %0;\n" :: "n"(N) : "memory");
}
__device__ __forceinline__ void ldsm_x4(uint32_t* r, uint32_t addr) {
    asm volatile("ldmatrix.sync.aligned.m8n8.x4.shared.b16 {%0,%1,%2,%3}, [%4];"
                 : "=r"(r[0]), "=r"(r[1]), "=r"(r[2]), "=r"(r[3]) : "r"(addr));
}
__device__ __forceinline__ void mma_bf16(float* c, const uint32_t* a, const uint32_t* b) {
    asm volatile(
        "mma.sync.aligned.m16n8k16.row.col.f32.bf16.bf16.f32 "
        "{%0,%1,%2,%3}, {%4,%5,%6,%7}, {%8,%9}, {%0,%1,%2,%3};"
        : "+f"(c[0]), "+f"(c[1]), "+f"(c[2]), "+f"(c[3])
        : "r"(a[0]), "r"(a[1]), "r"(a[2]), "r"(a[3]), "r"(b[0]), "r"(b[1]));
}

// packed f32x2 helpers (sm_100+ PTX, not 'a'-gated)
__device__ __forceinline__ unsigned long long pack2(float x, float y) {
    unsigned long long r;
    asm("mov.b64 %0, {%1, %2};" : "=l"(r) : "f"(x), "f"(y));
    return r;
}
#define FMA2(acc, a, b) \
    asm("fma.rn.f32x2 %0, %1, %2, %0;" : "+l"(acc) : "l"(a), "l"(b))
#define ADD2(r, a, b) \
    asm("add.rn.f32x2 %0, %1, %2;" : "=l"(r) : "l"(a), "l"(b))

// ---------------- split fp32 -> bf16 hi + lo --------------------------------
__global__ void __launch_bounds__(256)
split_bf16(const float* __restrict__ in, __nv_bfloat16* __restrict__ hi,
           __nv_bfloat16* __restrict__ lo, size_t n)
{
    size_t i = ((size_t)blockIdx.x * 256 + threadIdx.x) * 4;
    if (i >= n) return;
    float4 v = *(const float4*)(in + i);
    __nv_bfloat16 h0 = __float2bfloat16(v.x);
    __nv_bfloat16 h1 = __float2bfloat16(v.y);
    __nv_bfloat16 h2 = __float2bfloat16(v.z);
    __nv_bfloat16 h3 = __float2bfloat16(v.w);
    __nv_bfloat16 l0 = __float2bfloat16(v.x - __bfloat162float(h0));
    __nv_bfloat16 l1 = __float2bfloat16(v.y - __bfloat162float(h1));
    __nv_bfloat16 l2 = __float2bfloat16(v.z - __bfloat162float(h2));
    __nv_bfloat16 l3 = __float2bfloat16(v.w - __bfloat162float(h3));
    __nv_bfloat162* H = (__nv_bfloat162*)(hi + i);
    __nv_bfloat162* L = (__nv_bfloat162*)(lo + i);
    H[0] = __nv_bfloat162(h0, h1); H[1] = __nv_bfloat162(h2, h3);
    L[0] = __nv_bfloat162(l0, l1); L[1] = __nv_bfloat162(l2, l3);
}

__global__ void zero_done() {
    if (threadIdx.x < N_CHUNKS) g_done[threadIdx.x] = 0;
}

// ---------------- GEMM tile geometry (worker path + GEMM2) -----------------
#define LDPB 144                     // padded row length in bytes (64 bf16 + pad)
#define ARR_BYTES (128 * LDPB)       // 18432 (128 rows)
#define STG_BYTES (4 * ARR_BYTES)    // 73728 (Ahi,Alo,Bhi,Blo per stage)
#define FUSED_SMEM (2 * STG_BYTES)   // 147456 (2-stage)

// ============================================================================
// FUSED FRONT: CTAs [0,32) = GRU scan (with inline conv); [32,148) = GEMM1
// workers producing z in s-chunk order, publishing g_done[chunk].
// ============================================================================
__global__ void __launch_bounds__(256, 1)
fused_front(const __nv_bfloat16* __restrict__ Ahi, const __nv_bfloat16* __restrict__ Alo,
            const __nv_bfloat16* __restrict__ Bhi, const __nv_bfloat16* __restrict__ Blo,
            const float* __restrict__ bias, float* __restrict__ Z,
            const float* __restrict__ sw,
            const float* __restrict__ cw, const float* __restrict__ cb,
            __nv_bfloat16* __restrict__ yh, __nv_bfloat16* __restrict__ yl)
{
    extern __shared__ char smem[];
    // scan statics (allocated in all CTAs; used only by scan CTAs)
    __shared__ __align__(16) unsigned long long h_pair[128];
    __shared__ __align__(16) unsigned long long rh_pair[128];
    __shared__ float sf[128];
    __shared__ unsigned long long pr[4][64], pf[4][64], pc[4][64];

    const int tid = threadIdx.x;

    if (blockIdx.x >= N_SCAN_CTAS) {
        // ================= GEMM1 worker =================
        const uint32_t su = smem_to_u32(smem);
        const int wk   = blockIdx.x - N_SCAN_CTAS;
        const int wid  = tid >> 5;
        const int lane = tid & 31;
        const int warp_m = wid >> 2;    // 0..1
        const int warp_n = wid & 3;     // 0..3
        const int K = INs;
        const int NCH = K >> 6;

        const uint32_t a_lane = (uint32_t)((lane & 15) * LDPB + (lane >> 4) * 16)
                              + (uint32_t)(warp_m * 64) * LDPB;
        const int g = lane >> 3;
        const uint32_t b_lane = (uint32_t)((((g >> 1) * 8) + (lane & 7)) * LDPB + (g & 1) * 16)
                              + (uint32_t)(warp_n * 32) * LDPB;

        for (int t = wk; t < N_TILES; t += N_WORKERS) {
            const int chunk = t / TILES_PER_CHUNK;
            const int sub   = t % TILES_PER_CHUNK;
            const int bsub  = sub / (CHs / 128);
            const int ncol  = sub % (CHs / 128);
            const int bm = bsub * Ss + chunk * CHUNK_S;   // 128 rows, one batch
            const int bn = ncol << 7;

            auto load_chunk = [&](int ci, int st) {
                uint32_t sb = su + (uint32_t)st * STG_BYTES;
                size_t kbase = (size_t)ci * 64;
#pragma unroll
                for (int u = 0; u < 4; u++) {
                    int s   = tid + u * 256;
                    int row = s >> 3;
                    int ks  = s & 7;
                    uint32_t so = (uint32_t)row * LDPB + (uint32_t)ks * 16;
                    size_t gA = (size_t)(bm + row) * K + kbase + ks * 8;
                    size_t gB = (size_t)(bn + row) * K + kbase + ks * 8;
                    cpa16(sb +                 so, Ahi + gA);
                    cpa16(sb + 1 * ARR_BYTES + so, Alo + gA);
                    cpa16(sb + 2 * ARR_BYTES + so, Bhi + gB);
                    cpa16(sb + 3 * ARR_BYTES + so, Blo + gB);
                }
                cpa_commit();
            };

            float acc[4][4][4];
#pragma unroll
            for (int i = 0; i < 4; i++)
#pragma unroll
                for (int j = 0; j < 4; j++)
#pragma unroll
                    for (int k = 0; k < 4; k++) acc[i][j][k] = 0.0f;

            load_chunk(0, 0);
            for (int i = 0; i < NCH; i++) {
                __syncthreads();
                if (i + 1 < NCH) load_chunk(i + 1, (i + 1) & 1);
                if (i + 1 < NCH) cpa_wait<1>(); else cpa_wait<0>();
                __syncthreads();

                uint32_t sb  = su + (uint32_t)(i & 1) * STG_BYTES;
                uint32_t ah  = sb + a_lane;
                uint32_t al  = sb + 1 * ARR_BYTES + a_lane;
                uint32_t bh  = sb + 2 * ARR_BYTES + b_lane;
                uint32_t bl  = sb + 3 * ARR_BYTES + b_lane;

#pragma unroll
                for (int ks = 0; ks < 4; ks++) {
                    uint32_t ko = (uint32_t)ks * 32;
                    uint32_t fa_h[4][4], fa_l[4][4];
                    uint32_t fb_h[4][2], fb_l[4][2];
#pragma unroll
                    for (int mi = 0; mi < 4; mi++) {
                        ldsm_x4(fa_h[mi], ah + (uint32_t)(mi * 16) * LDPB + ko);
                        ldsm_x4(fa_l[mi], al + (uint32_t)(mi * 16) * LDPB + ko);
                    }
#pragma unroll
                    for (int p = 0; p < 2; p++) {
                        uint32_t r[4];
                        ldsm_x4(r, bh + (uint32_t)(p * 16) * LDPB + ko);
                        fb_h[p * 2 + 0][0] = r[0]; fb_h[p * 2 + 0][1] = r[1];
                        fb_h[p * 2 + 1][0] = r[2]; fb_h[p * 2 + 1][1] = r[3];
                        ldsm_x4(r, bl + (uint32_t)(p * 16) * LDPB + ko);
                        fb_l[p * 2 + 0][0] = r[0]; fb_l[p * 2 + 0][1] = r[1];
                        fb_l[p * 2 + 1][0] = r[2]; fb_l[p * 2 + 1][1] = r[3];
                    }
#pragma unroll
                    for (int mi = 0; mi < 4; mi++)
#pragma unroll
                        for (int ni = 0; ni < 4; ni++) {
                            mma_bf16(acc[mi][ni], fa_h[mi], fb_h[ni]);
                            mma_bf16(acc[mi][ni], fa_h[mi], fb_l[ni]);
                            mma_bf16(acc[mi][ni], fa_l[mi], fb_h[ni]);
                        }
                }
            }

            // epilogue: bias + tanh -> z
            const int gid = lane >> 2;
            const int tig = lane & 3;
#pragma unroll
            for (int mi = 0; mi < 4; mi++) {
                int row0 = bm + warp_m * 64 + mi * 16 + gid;
#pragma unroll
                for (int ni = 0; ni < 4; ni++) {
                    int col = bn + warp_n * 32 + ni * 8 + tig * 2;
                    float b0 = bias[col], b1 = bias[col + 1];
                    float v0 = fast_tanh(acc[mi][ni][0] + b0);
                    float v1 = fast_tanh(acc[mi][ni][1] + b1);
                    float v2 = fast_tanh(acc[mi][ni][2] + b0);
                    float v3 = fast_tanh(acc[mi][ni][3] + b1);
                    *(float2*)(Z + (size_t)row0 * CHs + col)       = make_float2(v0, v1);
                    *(float2*)(Z + (size_t)(row0 + 8) * CHs + col) = make_float2(v2, v3);
                }
            }

            __threadfence();
            __syncthreads();
            if (tid == 0) atomicAdd(&g_done[chunk], 1);
        }
        return;
    }

    // ================= GRU scan (v3) + inline conv =================
    const int b   = blockIdx.x >> 4;
    const int hh  = blockIdx.x & 15;
    const int c2  = tid & 63;
    const int q   = tid >> 6;
    const int d0  = q << 5;

    const float* wc_g = sw + (size_t)(hh)      * Dd * Dd;  // cand
    const float* wf_g = sw + (size_t)(16 + hh) * Dd * Dd;  // forget
    const float* wr_g = sw + (size_t)(32 + hh) * Dd * Dd;  // reset

    unsigned long long wc[32], wf[32], wr[32];
#pragma unroll
    for (int j = 0; j < 32; j++) {
        float2 t;
        t = *(const float2*)(wc_g + (size_t)(d0 + j) * 128 + 2 * c2);
        wc[j] = pack2(t.x * FACTOR_, t.y * FACTOR_);
        t = *(const float2*)(wf_g + (size_t)(d0 + j) * 128 + 2 * c2);
        wf[j] = pack2(t.x * FACTOR_, t.y * FACTOR_);
        t = *(const float2*)(wr_g + (size_t)(d0 + j) * 128 + 2 * c2);
        wr[j] = pack2(t.x * FACTOR_, t.y * FACTOR_);
    }
    if (tid < 128) h_pair[tid] = 0ULL;

    // finalizer (tid<128): one column; conv taps kept in registers
    const int col = hh * 128 + tid;
    const float* zb = Z + (size_t)b * Ss * CHs;
    __nv_bfloat16* yhb = yh + (size_t)b * Ss * STATEs + col;
    __nv_bfloat16* ylb = yl + (size_t)b * Ss * STATEs + col;
    const float* prf = (const float*)pr;   // [4][128] view
    const float* pff = (const float*)pf;
    const float* pcf = (const float*)pc;

    float cwi0=0,cwi1=0,cwi2=0,cwi3=0, cwf0=0,cwf1=0,cwf2=0,cwf3=0;
    float cwr0=0,cwr1=0,cwr2=0,cwr3=0, cbi=0, cbf=0, cbr=0;
    if (tid < 128) {
        const float4 wi = *(const float4*)(cw + (size_t)col * 4);
        const float4 wfv = *(const float4*)(cw + (size_t)(2048 + col) * 4);
        const float4 wrv = *(const float4*)(cw + (size_t)(4096 + col) * 4);
        cwi0=wi.x; cwi1=wi.y; cwi2=wi.z; cwi3=wi.w;
        cwf0=wfv.x; cwf1=wfv.y; cwf2=wfv.z; cwf3=wfv.w;
        cwr0=wrv.x; cwr1=wrv.y; cwr2=wrv.z; cwr3=wrv.w;
        cbi = cb[col]; cbf = cb[2048 + col]; cbr = cb[4096 + col];
    }
    __syncthreads();

    // wait for first chunk of z, then prime the window
    {
        volatile int* p = &g_done[0];
        while (*p < TILES_PER_CHUNK) { __nanosleep(128); }
        __threadfence();
    }
    float xi0=0,xi1=0,xi2=0, xf0=0,xf1=0,xf2=0, xr0=0,xr1=0,xr2=0;
    float cur_i=0, cur_f=0, cur_r=0;
    if (tid < 128) {
        cur_i = zb[col];
        cur_f = zb[2048 + col];
        cur_r = zb[4096 + col];
    }
    float hcur = 0.f;

    for (int s = 0; s < Ss; s++) {
        // conv outputs for this step (fp32, same tap order as before)
        float zci=0, zcf=0, zcr=0;
        if (tid < 128) {
            zci = (cwi0*xi0 + cwi1*xi1 + cwi2*xi2 + cwi3*cur_i + cbi) * FACTOR_;
            zcf = (cwf0*xf0 + cwf1*xf1 + cwf2*xf2 + cwf3*cur_f + cbf) * FACTOR_;
            zcr = (cwr0*xr0 + cwr1*xr1 + cwr2*xr2 + cwr3*cur_r + cbr) * FACTOR_;
        }

        // chunk gate BEFORE prefetching z[s+1]
        if ((s & (CHUNK_S - 1)) == (CHUNK_S - 1) && s + 1 < Ss) {
            volatile int* p = &g_done[(s + 1) >> 7];
            while (*p < TILES_PER_CHUNK) { __nanosleep(128); }
            __threadfence();
        }

        float ni = 0.f, nf = 0.f, nr = 0.f;
        if (tid < 128 && s + 1 < Ss) {
            const float* zs = zb + (size_t)(s + 1) * CHs;
            ni = zs[col];
            nf = zs[2048 + col];
            nr = zs[4096 + col];
        }

        // phase 1: partial r/f over d in [d0, d0+32), 2 accums per gate
        unsigned long long ar0 = 0ULL, ar1 = 0ULL, af0 = 0ULL, af1 = 0ULL;
        {
            const ulonglong2* hp = (const ulonglong2*)(h_pair + d0);
#pragma unroll
            for (int j = 0; j < 16; j++) {
                ulonglong2 hv = hp[j];
                FMA2(ar0, hv.x, wr[2 * j]);
                FMA2(af0, hv.x, wf[2 * j]);
                FMA2(ar1, hv.y, wr[2 * j + 1]);
                FMA2(af1, hv.y, wf[2 * j + 1]);
            }
        }
        unsigned long long art, aft;
        ADD2(art, ar0, ar1);
        ADD2(aft, af0, af1);
        pr[q][c2] = art;
        pf[q][c2] = aft;
        __syncthreads();

        float ff = 0.f;
        if (tid < 128) {
            float rs = zcr + prf[tid] + prf[128 + tid] + prf[256 + tid] + prf[384 + tid];
            float fs = zcf + pff[tid] + pff[128 + tid] + pff[256 + tid] + pff[384 + tid];
            float r  = fast_sigmoid(rs);
            ff = fast_sigmoid(fs);
            float rh = r * hcur;
            rh_pair[tid] = pack2(rh, rh);
            sf[tid] = ff;
        }
        __syncthreads();

        // phase 2: partial cand on (r*h)
        unsigned long long ac0 = 0ULL, ac1 = 0ULL;
        {
            const ulonglong2* rp = (const ulonglong2*)(rh_pair + d0);
#pragma unroll
            for (int j = 0; j < 16; j++) {
                ulonglong2 hv = rp[j];
                FMA2(ac0, hv.x, wc[2 * j]);
                FMA2(ac1, hv.y, wc[2 * j + 1]);
            }
        }
        unsigned long long act;
        ADD2(act, ac0, ac1);
        pc[q][c2] = act;
        __syncthreads();

        if (tid < 128) {
            float cs = zci + pcf[tid] + pcf[128 + tid] + pcf[256 + tid] + pcf[384 + tid];
            float cd = fast_tanh(cs);
            float hn = fmaf(ff, hcur - cd, cd);   // f*h + (1-f)*cand
            hcur = hn;
            h_pair[tid] = pack2(hn, hn);
            __nv_bfloat16 bh = __float2bfloat16(hn);
            yhb[(size_t)s * STATEs] = bh;
            ylb[(size_t)s * STATEs] = __float2bfloat16(hn - __bfloat162float(bh));
            // shift conv windows
            xi0 = xi1; xi1 = xi2; xi2 = cur_i; cur_i = ni;
            xf0 = xf1; xf1 = xf2; xf2 = cur_f; cur_f = nf;
            xr0 = xr1; xr1 = xr2; xr2 = cur_r; cur_r = nr;
        }
        __syncthreads();
    }
}

// ---------------- GEMM2 (R8, proven): C = A * B^T, 256x128 tiles, 512 thr --
#define A_ROWS2 256
#define A_BYTES2 (A_ROWS2 * LDPB)                 // 36864
#define B_BYTES2 (128 * LDPB)                     // 18432
#define STG_BYTES2 (2 * A_BYTES2 + 2 * B_BYTES2)  // 110592
#define GEMM2_SMEM (2 * STG_BYTES2)               // 221184

__global__ void __launch_bounds__(512)
mma_gemm2(const __nv_bfloat16* __restrict__ Ahi, const __nv_bfloat16* __restrict__ Alo,
          const __nv_bfloat16* __restrict__ Bhi, const __nv_bfloat16* __restrict__ Blo,
          float* __restrict__ C, int M, int N, int K)
{
    extern __shared__ char smem[];
    const uint32_t su = smem_to_u32(smem);
    const int tid  = threadIdx.x;
    const int wid  = tid >> 5;
    const int lane = tid & 31;
    const int bm   = blockIdx.y << 8;
    const int bn   = blockIdx.x << 7;
    const int warp_m = wid >> 2;
    const int warp_n = wid & 3;

    const int NCH = K >> 6;

    auto load_chunk = [&](int ci, int st) {
        uint32_t sb = su + (uint32_t)st * STG_BYTES2;
        size_t kbase = (size_t)ci * 64;
#pragma unroll
        for (int t = 0; t < 4; t++) {
            int s   = tid + t * 512;
            int row = s >> 3;
            int ks  = s & 7;
            uint32_t so = (uint32_t)row * LDPB + (uint32_t)ks * 16;
            size_t gA = (size_t)(bm + row) * K + kbase + ks * 8;
            cpa16(sb +            so, Ahi + gA);
            cpa16(sb + A_BYTES2 + so, Alo + gA);
        }
#pragma unroll
        for (int t = 0; t < 2; t++) {
            int s   = tid + t * 512;
            int row = s >> 3;
            int ks  = s & 7;
            uint32_t so = (uint32_t)row * LDPB + (uint32_t)ks * 16;
            size_t gB = (size_t)(bn + row) * K + kbase + ks * 8;
            cpa16(sb + 2 * A_BYTES2 +            so, Bhi + gB);
            cpa16(sb + 2 * A_BYTES2 + B_BYTES2 + so, Blo + gB);
        }
        cpa_commit();
    };

    float acc[4][4][4];
#pragma unroll
    for (int i = 0; i < 4; i++)
#pragma unroll
        for (int j = 0; j < 4; j++)
#pragma unroll
            for (int k = 0; k < 4; k++) acc[i][j][k] = 0.0f;

    const uint32_t a_lane = (uint32_t)((lane & 15) * LDPB + (lane >> 4) * 16)
                          + (uint32_t)(warp_m * 64) * LDPB;
    const int g = lane >> 3;
    const uint32_t b_lane = (uint32_t)((((g >> 1) * 8) + (lane & 7)) * LDPB + (g & 1) * 16)
                          + (uint32_t)(warp_n * 32) * LDPB;

    load_chunk(0, 0);

    for (int i = 0; i < NCH; i++) {
        __syncthreads();
        if (i + 1 < NCH) load_chunk(i + 1, (i + 1) & 1);
        if (i + 1 < NCH) cpa_wait<1>(); else cpa_wait<0>();
        __syncthreads();

        uint32_t sb  = su + (uint32_t)(i & 1) * STG_BYTES2;
        uint32_t ah  = sb + a_lane;
        uint32_t al  = sb + A_BYTES2 + a_lane;
        uint32_t bh  = sb + 2 * A_BYTES2 + b_lane;
        uint32_t bl  = sb + 2 * A_BYTES2 + B_BYTES2 + b_lane;

#pragma unroll
        for (int ks = 0; ks < 4; ks++) {
            uint32_t ko = (uint32_t)ks * 32;
            uint32_t fa_h[4][4], fa_l[4][4];
            uint32_t fb_h[4][2], fb_l[4][2];
#pragma unroll
            for (int mi = 0; mi < 4; mi++) {
                ldsm_x4(fa_h[mi], ah + (uint32_t)(mi * 16) * LDPB + ko);
                ldsm_x4(fa_l[mi], al + (uint32_t)(mi * 16) * LDPB + ko);
            }
#pragma unroll
            for (int p = 0; p < 2; p++) {
                uint32_t r[4];
                ldsm_x4(r, bh + (uint32_t)(p * 16) * LDPB + ko);
                fb_h[p * 2 + 0][0] = r[0]; fb_h[p * 2 + 0][1] = r[1];
                fb_h[p * 2 + 1][0] = r[2]; fb_h[p * 2 + 1][1] = r[3];
                ldsm_x4(r, bl + (uint32_t)(p * 16) * LDPB + ko);
                fb_l[p * 2 + 0][0] = r[0]; fb_l[p * 2 + 0][1] = r[1];
                fb_l[p * 2 + 1][0] = r[2]; fb_l[p * 2 + 1][1] = r[3];
            }
#pragma unroll
            for (int mi = 0; mi < 4; mi++)
#pragma unroll
                for (int ni = 0; ni < 4; ni++) {
                    mma_bf16(acc[mi][ni], fa_h[mi], fb_h[ni]);
                    mma_bf16(acc[mi][ni], fa_h[mi], fb_l[ni]);
                    mma_bf16(acc[mi][ni], fa_l[mi], fb_h[ni]);
                }
        }
    }

    const int gid = lane >> 2;
    const int tig = lane & 3;
#pragma unroll
    for (int mi = 0; mi < 4; mi++) {
        int row0 = bm + warp_m * 64 + mi * 16 + gid;
#pragma unroll
        for (int ni = 0; ni < 4; ni++) {
            int col = bn + warp_n * 32 + ni * 8 + tig * 2;
            *(float2*)(C + (size_t)row0 * N + col)
                = make_float2(acc[mi][ni][0], acc[mi][ni][1]);
            *(float2*)(C + (size_t)(row0 + 8) * N + col)
                = make_float2(acc[mi][ni][2], acc[mi][ni][3]);
        }
    }
}

// ---------------- launch ----------------
extern "C" void kernel_launch(void* const* d_in, const int* in_sizes, int n_in,
                              void* d_out, int out_size)
{
    const float* x    = (const float*)d_in[0];
    const float* w_in = (const float*)d_in[1];
    const float* b_in = (const float*)d_in[2];
    const float* cw   = (const float*)d_in[3];
    const float* cb   = (const float*)d_in[4];
    const float* swt  = (const float*)d_in[5];
    const float* wout = (const float*)d_in[6];
    float* out = (float*)d_out;

    float* zp;
    cudaGetSymbolAddress((void**)&zp, g_z);
    __nv_bfloat16 *xh, *xl, *wh, *wl, *yh, *yl, *oh, *ol;
    cudaGetSymbolAddress((void**)&xh, g_xhi);
    cudaGetSymbolAddress((void**)&xl, g_xlo);
    cudaGetSymbolAddress((void**)&wh, g_whi);
    cudaGetSymbolAddress((void**)&wl, g_wlo);
    cudaGetSymbolAddress((void**)&yh, g_yhi);
    cudaGetSymbolAddress((void**)&yl, g_ylo);
    cudaGetSymbolAddress((void**)&oh, g_ohi);
    cudaGetSymbolAddress((void**)&ol, g_olo);

    // splits + flag reset
    {
        size_t nx = (size_t)Bb * Ss * INs;
        split_bf16<<<(int)(nx / 1024), 256>>>(x, xh, xl, nx);
        size_t nw = (size_t)CHs * INs;
        split_bf16<<<(int)(nw / 1024), 256>>>(w_in, wh, wl, nw);
        size_t no = (size_t)OUTs * STATEs;
        split_bf16<<<(int)(no / 1024), 256>>>(wout, oh, ol, no);
        zero_done<<<1, 32>>>();
    }

    // fused GEMM1 + conv + scan
    {
        cudaFuncSetAttribute(fused_front,
                             cudaFuncAttributeMaxDynamicSharedMemorySize,
                             FUSED_SMEM);
        fused_front<<<N_SCAN_CTAS + N_WORKERS, 256, FUSED_SMEM>>>(
            xh, xl, wh, wl, b_in, zp, swt, cw, cb, yh, yl);
    }

    // GEMM2: out = y @ w_out^T
    {
        cudaFuncSetAttribute(mma_gemm2,
                             cudaFuncAttributeMaxDynamicSharedMemorySize,
                             GEMM2_SMEM);
        dim3 grid(OUTs / 128, (Bb * Ss) / 256);
        mma_gemm2<<<grid, 512, GEMM2_SMEM>>>(
            yh, yl, oh, ol, out, Bb * Ss, OUTs, STATEs);
    }
}

// round 10
// speedup vs baseline: 3.6018x; 1.1561x over previous
#include <cuda_runtime.h>
#include <cuda_bf16.h>
#include <math.h>
#include <stdint.h>

// Problem constants
#define Bb 2
#define Ss 4096
#define INs 2048
#define STATEs 2048
#define OUTs 2048
#define Hh 16
#define Dd 128
#define CHs 6144               // 3*STATE
#define FACTOR_ 0.0214373219f  // 1/sqrt(2048+128)

#define N_SCAN_CTAS 32
#define N_WORKERS   116
#define CHUNK_S     128        // s-steps per completion chunk
#define N_CHUNKS    (Ss / CHUNK_S)          // 32
#define TILES_PER_CHUNK (2 * (CHs / 128))   // 96
#define N_TILES     (N_CHUNKS * TILES_PER_CHUNK)  // 3072  (GEMM1)
#define N_TILES2    ((Bb * Ss / 128) * (OUTs / 128))  // 1024 (GEMM2)

// ---------------- scratch (device globals: allocation-free) ----------------
__device__ float g_z [(size_t)Bb * Ss * CHs];    // after GEMM1+tanh
__device__ int   g_done [N_CHUNKS];              // z chunk counters (96 each)
__device__ int   g_ydone[Bb * N_CHUNKS];         // y chunk counters (16 each)

// bf16 hi/lo split buffers
__device__ __nv_bfloat16 g_xhi[(size_t)Bb * Ss * INs];
__device__ __nv_bfloat16 g_xlo[(size_t)Bb * Ss * INs];
__device__ __nv_bfloat16 g_whi[(size_t)CHs * INs];
__device__ __nv_bfloat16 g_wlo[(size_t)CHs * INs];
__device__ __nv_bfloat16 g_yhi[(size_t)Bb * Ss * STATEs];
__device__ __nv_bfloat16 g_ylo[(size_t)Bb * Ss * STATEs];
__device__ __nv_bfloat16 g_ohi[(size_t)OUTs * STATEs];
__device__ __nv_bfloat16 g_olo[(size_t)OUTs * STATEs];

// ---------------- math helpers ----------------
__device__ __forceinline__ float fast_tanh(float x) {
    float e = __expf(2.0f * x);
    return 1.0f - 2.0f / (e + 1.0f);
}
__device__ __forceinline__ float fast_sigmoid(float x) {
    return 1.0f / (1.0f + __expf(-x));
}

__device__ __forceinline__ uint32_t smem_to_u32(const void* p) {
    uint32_t a;
    asm("{ .reg .u64 t; cvta.to.shared.u64 t, %1; cvt.u32.u64 %0, t; }"
        : "=r"(a) : "l"(p));
    return a;
}
__device__ __forceinline__ void cpa16(uint32_t s, const void* g) {
    asm volatile("cp.async.cg.shared.global [%0], [%1], 16;\n"
                 :: "r"(s), "l"(g) : "memory");
}
__device__ __forceinline__ void cpa_commit() {
    asm volatile("cp.async.commit_group;\n" ::: "memory");
}
template <int N>
__device__ __forceinline__ void cpa_wait() {
    asm volatile("cp.async.wait_group %0;\n" :: "n"(N) : "memory");
}
__device__ __forceinline__ void ldsm_x4(uint32_t* r, uint32_t addr) {
    asm volatile("ldmatrix.sync.aligned.m8n8.x4.shared.b16 {%0,%1,%2,%3}, [%4];"
                 : "=r"(r[0]), "=r"(r[1]), "=r"(r[2]), "=r"(r[3]) : "r"(addr));
}
__device__ __forceinline__ void mma_bf16(float* c, const uint32_t* a, const uint32_t* b) {
    asm volatile(
        "mma.sync.aligned.m16n8k16.row.col.f32.bf16.bf16.f32 "
        "{%0,%1,%2,%3}, {%4,%5,%6,%7}, {%8,%9}, {%0,%1,%2,%3};"
        : "+f"(c[0]), "+f"(c[1]), "+f"(c[2]), "+f"(c[3])
        : "r"(a[0]), "r"(a[1]), "r"(a[2]), "r"(a[3]), "r"(b[0]), "r"(b[1]));
}

// packed f32x2 helpers (sm_100+ PTX, not 'a'-gated)
__device__ __forceinline__ unsigned long long pack2(float x, float y) {
    unsigned long long r;
    asm("mov.b64 %0, {%1, %2};" : "=l"(r) : "f"(x), "f"(y));
    return r;
}
#define FMA2(acc, a, b) \
    asm("fma.rn.f32x2 %0, %1, %2, %0;" : "+l"(acc) : "l"(a), "l"(b))
#define ADD2(r, a, b) \
    asm("add.rn.f32x2 %0, %1, %2;" : "=l"(r) : "l"(a), "l"(b))

// ---------------- split fp32 -> bf16 hi + lo --------------------------------
__global__ void __launch_bounds__(256)
split_bf16(const float* __restrict__ in, __nv_bfloat16* __restrict__ hi,
           __nv_bfloat16* __restrict__ lo, size_t n)
{
    size_t i = ((size_t)blockIdx.x * 256 + threadIdx.x) * 4;
    if (i >= n) return;
    float4 v = *(const float4*)(in + i);
    __nv_bfloat16 h0 = __float2bfloat16(v.x);
    __nv_bfloat16 h1 = __float2bfloat16(v.y);
    __nv_bfloat16 h2 = __float2bfloat16(v.z);
    __nv_bfloat16 h3 = __float2bfloat16(v.w);
    __nv_bfloat16 l0 = __float2bfloat16(v.x - __bfloat162float(h0));
    __nv_bfloat16 l1 = __float2bfloat16(v.y - __bfloat162float(h1));
    __nv_bfloat16 l2 = __float2bfloat16(v.z - __bfloat162float(h2));
    __nv_bfloat16 l3 = __float2bfloat16(v.w - __bfloat162float(h3));
    __nv_bfloat162* H = (__nv_bfloat162*)(hi + i);
    __nv_bfloat162* L = (__nv_bfloat162*)(lo + i);
    H[0] = __nv_bfloat162(h0, h1); H[1] = __nv_bfloat162(h2, h3);
    L[0] = __nv_bfloat162(l0, l1); L[1] = __nv_bfloat162(l2, l3);
}

__global__ void zero_done() {
    int i = threadIdx.x;
    if (i < N_CHUNKS) g_done[i] = 0;
    if (i < Bb * N_CHUNKS) g_ydone[i] = 0;
}

// ---------------- GEMM tile geometry ----------------------------------------
#define LDPB 144                     // padded row length in bytes (64 bf16 + pad)
#define ARR_BYTES (128 * LDPB)       // 18432 (128 rows)
#define STG_BYTES (4 * ARR_BYTES)    // 73728 (Ahi,Alo,Bhi,Blo per stage)
#define FUSED_SMEM (2 * STG_BYTES)   // 147456 (2-stage)

// ============================================================================
// FUSED: CTAs [0,32) = GRU scan (inline conv, publishes y chunks);
// CTAs [32,148) = workers: 3072 GEMM1 tiles (publish z chunks), then
// 1024 GEMM2 tiles gated on y chunks. One persistent launch.
// ============================================================================
__global__ void __launch_bounds__(256, 1)
fused_all(const __nv_bfloat16* __restrict__ Ahi, const __nv_bfloat16* __restrict__ Alo,
          const __nv_bfloat16* __restrict__ Bhi, const __nv_bfloat16* __restrict__ Blo,
          const float* __restrict__ bias, float* __restrict__ Z,
          const float* __restrict__ sw,
          const float* __restrict__ cw, const float* __restrict__ cb,
          __nv_bfloat16* __restrict__ yh, __nv_bfloat16* __restrict__ yl,
          const __nv_bfloat16* __restrict__ Ohi, const __nv_bfloat16* __restrict__ Olo,
          float* __restrict__ Out)
{
    extern __shared__ char smem[];
    __shared__ __align__(16) unsigned long long h_pair[128];
    __shared__ __align__(16) unsigned long long rh_pair[128];
    __shared__ float sf[128];
    __shared__ unsigned long long pr[4][64], pf[4][64], pc[4][64];

    const int tid = threadIdx.x;

    if (blockIdx.x >= N_SCAN_CTAS) {
        // ================= worker: GEMM1 tiles then GEMM2 tiles =============
        const uint32_t su = smem_to_u32(smem);
        const int wk   = blockIdx.x - N_SCAN_CTAS;
        const int wid  = tid >> 5;
        const int lane = tid & 31;
        const int warp_m = wid >> 2;    // 0..1
        const int warp_n = wid & 3;     // 0..3
        const int K = INs;              // 2048 for both GEMMs
        const int NCH = K >> 6;

        const uint32_t a_lane = (uint32_t)((lane & 15) * LDPB + (lane >> 4) * 16)
                              + (uint32_t)(warp_m * 64) * LDPB;
        const int g = lane >> 3;
        const uint32_t b_lane = (uint32_t)((((g >> 1) * 8) + (lane & 7)) * LDPB + (g & 1) * 16)
                              + (uint32_t)(warp_n * 32) * LDPB;

        const __nv_bfloat16 *tA0, *tA1, *tB0, *tB1;
        int bm, bn, chunk = 0;
        bool g1;

        for (int t = wk; t < N_TILES + N_TILES2; t += N_WORKERS) {
            if (t < N_TILES) {
                g1 = true;
                chunk = t / TILES_PER_CHUNK;
                const int sub  = t % TILES_PER_CHUNK;
                const int bsub = sub / (CHs / 128);
                const int ncol = sub % (CHs / 128);
                bm = bsub * Ss + chunk * CHUNK_S;
                bn = ncol << 7;
                tA0 = Ahi; tA1 = Alo; tB0 = Bhi; tB1 = Blo;
            } else {
                g1 = false;
                const int tt   = t - N_TILES;
                const int c    = tt >> 5;         // chunk-major ordering
                const int sub  = tt & 31;
                const int bsub = sub >> 4;
                const int ncol = sub & 15;
                bm = bsub * Ss + c * CHUNK_S;
                bn = ncol << 7;
                tA0 = yh; tA1 = yl; tB0 = Ohi; tB1 = Olo;
                // gate on y chunk availability (scan publishes 16 arrivals)
                if (tid == 0) {
                    volatile int* p = &g_ydone[bsub * N_CHUNKS + c];
                    while (*p < Hh) { __nanosleep(128); }
                }
                __syncthreads();
                __threadfence();
            }

            auto load_chunk = [&](int ci, int st) {
                uint32_t sb = su + (uint32_t)st * STG_BYTES;
                size_t kbase = (size_t)ci * 64;
#pragma unroll
                for (int u = 0; u < 4; u++) {
                    int s   = tid + u * 256;
                    int row = s >> 3;
                    int ks  = s & 7;
                    uint32_t so = (uint32_t)row * LDPB + (uint32_t)ks * 16;
                    size_t gA = (size_t)(bm + row) * K + kbase + ks * 8;
                    size_t gB = (size_t)(bn + row) * K + kbase + ks * 8;
                    cpa16(sb +                 so, tA0 + gA);
                    cpa16(sb + 1 * ARR_BYTES + so, tA1 + gA);
                    cpa16(sb + 2 * ARR_BYTES + so, tB0 + gB);
                    cpa16(sb + 3 * ARR_BYTES + so, tB1 + gB);
                }
                cpa_commit();
            };

            float acc[4][4][4];
#pragma unroll
            for (int i = 0; i < 4; i++)
#pragma unroll
                for (int j = 0; j < 4; j++)
#pragma unroll
                    for (int k = 0; k < 4; k++) acc[i][j][k] = 0.0f;

            load_chunk(0, 0);
            for (int i = 0; i < NCH; i++) {
                __syncthreads();
                if (i + 1 < NCH) load_chunk(i + 1, (i + 1) & 1);
                if (i + 1 < NCH) cpa_wait<1>(); else cpa_wait<0>();
                __syncthreads();

                uint32_t sb  = su + (uint32_t)(i & 1) * STG_BYTES;
                uint32_t ah  = sb + a_lane;
                uint32_t al  = sb + 1 * ARR_BYTES + a_lane;
                uint32_t bh  = sb + 2 * ARR_BYTES + b_lane;
                uint32_t bl  = sb + 3 * ARR_BYTES + b_lane;

#pragma unroll
                for (int ks = 0; ks < 4; ks++) {
                    uint32_t ko = (uint32_t)ks * 32;
                    uint32_t fa_h[4][4], fa_l[4][4];
                    uint32_t fb_h[4][2], fb_l[4][2];
#pragma unroll
                    for (int mi = 0; mi < 4; mi++) {
                        ldsm_x4(fa_h[mi], ah + (uint32_t)(mi * 16) * LDPB + ko);
                        ldsm_x4(fa_l[mi], al + (uint32_t)(mi * 16) * LDPB + ko);
                    }
#pragma unroll
                    for (int p = 0; p < 2; p++) {
                        uint32_t r[4];
                        ldsm_x4(r, bh + (uint32_t)(p * 16) * LDPB + ko);
                        fb_h[p * 2 + 0][0] = r[0]; fb_h[p * 2 + 0][1] = r[1];
                        fb_h[p * 2 + 1][0] = r[2]; fb_h[p * 2 + 1][1] = r[3];
                        ldsm_x4(r, bl + (uint32_t)(p * 16) * LDPB + ko);
                        fb_l[p * 2 + 0][0] = r[0]; fb_l[p * 2 + 0][1] = r[1];
                        fb_l[p * 2 + 1][0] = r[2]; fb_l[p * 2 + 1][1] = r[3];
                    }
#pragma unroll
                    for (int mi = 0; mi < 4; mi++)
#pragma unroll
                        for (int ni = 0; ni < 4; ni++) {
                            mma_bf16(acc[mi][ni], fa_h[mi], fb_h[ni]);
                            mma_bf16(acc[mi][ni], fa_h[mi], fb_l[ni]);
                            mma_bf16(acc[mi][ni], fa_l[mi], fb_h[ni]);
                        }
                }
            }

            const int gid = lane >> 2;
            const int tig = lane & 3;
            if (g1) {
                // epilogue: bias + tanh -> Z, publish z chunk
#pragma unroll
                for (int mi = 0; mi < 4; mi++) {
                    int row0 = bm + warp_m * 64 + mi * 16 + gid;
#pragma unroll
                    for (int ni = 0; ni < 4; ni++) {
                        int col = bn + warp_n * 32 + ni * 8 + tig * 2;
                        float b0 = bias[col], b1 = bias[col + 1];
                        float v0 = fast_tanh(acc[mi][ni][0] + b0);
                        float v1 = fast_tanh(acc[mi][ni][1] + b1);
                        float v2 = fast_tanh(acc[mi][ni][2] + b0);
                        float v3 = fast_tanh(acc[mi][ni][3] + b1);
                        *(float2*)(Z + (size_t)row0 * CHs + col)       = make_float2(v0, v1);
                        *(float2*)(Z + (size_t)(row0 + 8) * CHs + col) = make_float2(v2, v3);
                    }
                }
                __threadfence();
                __syncthreads();
                if (tid == 0) atomicAdd(&g_done[chunk], 1);
            } else {
                // epilogue: plain store -> Out
#pragma unroll
                for (int mi = 0; mi < 4; mi++) {
                    int row0 = bm + warp_m * 64 + mi * 16 + gid;
#pragma unroll
                    for (int ni = 0; ni < 4; ni++) {
                        int col = bn + warp_n * 32 + ni * 8 + tig * 2;
                        *(float2*)(Out + (size_t)row0 * OUTs + col)
                            = make_float2(acc[mi][ni][0], acc[mi][ni][1]);
                        *(float2*)(Out + (size_t)(row0 + 8) * OUTs + col)
                            = make_float2(acc[mi][ni][2], acc[mi][ni][3]);
                    }
                }
            }
        }
        return;
    }

    // ================= GRU scan (v3) + inline conv + y publication =========
    const int b   = blockIdx.x >> 4;
    const int hh  = blockIdx.x & 15;
    const int c2  = tid & 63;
    const int q   = tid >> 6;
    const int d0  = q << 5;

    const float* wc_g = sw + (size_t)(hh)      * Dd * Dd;  // cand
    const float* wf_g = sw + (size_t)(16 + hh) * Dd * Dd;  // forget
    const float* wr_g = sw + (size_t)(32 + hh) * Dd * Dd;  // reset

    unsigned long long wc[32], wf[32], wr[32];
#pragma unroll
    for (int j = 0; j < 32; j++) {
        float2 t;
        t = *(const float2*)(wc_g + (size_t)(d0 + j) * 128 + 2 * c2);
        wc[j] = pack2(t.x * FACTOR_, t.y * FACTOR_);
        t = *(const float2*)(wf_g + (size_t)(d0 + j) * 128 + 2 * c2);
        wf[j] = pack2(t.x * FACTOR_, t.y * FACTOR_);
        t = *(const float2*)(wr_g + (size_t)(d0 + j) * 128 + 2 * c2);
        wr[j] = pack2(t.x * FACTOR_, t.y * FACTOR_);
    }
    if (tid < 128) h_pair[tid] = 0ULL;

    const int col = hh * 128 + tid;
    const float* zb = Z + (size_t)b * Ss * CHs;
    __nv_bfloat16* yhb = yh + (size_t)b * Ss * STATEs + col;
    __nv_bfloat16* ylb = yl + (size_t)b * Ss * STATEs + col;
    const float* prf = (const float*)pr;
    const float* pff = (const float*)pf;
    const float* pcf = (const float*)pc;

    float cwi0=0,cwi1=0,cwi2=0,cwi3=0, cwf0=0,cwf1=0,cwf2=0,cwf3=0;
    float cwr0=0,cwr1=0,cwr2=0,cwr3=0, cbi=0, cbf=0, cbr=0;
    if (tid < 128) {
        const float4 wi  = *(const float4*)(cw + (size_t)col * 4);
        const float4 wfv = *(const float4*)(cw + (size_t)(2048 + col) * 4);
        const float4 wrv = *(const float4*)(cw + (size_t)(4096 + col) * 4);
        cwi0=wi.x; cwi1=wi.y; cwi2=wi.z; cwi3=wi.w;
        cwf0=wfv.x; cwf1=wfv.y; cwf2=wfv.z; cwf3=wfv.w;
        cwr0=wrv.x; cwr1=wrv.y; cwr2=wrv.z; cwr3=wrv.w;
        cbi = cb[col]; cbf = cb[2048 + col]; cbr = cb[4096 + col];
    }
    __syncthreads();

    {
        volatile int* p = &g_done[0];
        while (*p < TILES_PER_CHUNK) { __nanosleep(128); }
        __threadfence();
    }
    float xi0=0,xi1=0,xi2=0, xf0=0,xf1=0,xf2=0, xr0=0,xr1=0,xr2=0;
    float cur_i=0, cur_f=0, cur_r=0;
    if (tid < 128) {
        cur_i = zb[col];
        cur_f = zb[2048 + col];
        cur_r = zb[4096 + col];
    }
    float hcur = 0.f;

    for (int s = 0; s < Ss; s++) {
        float zci=0, zcf=0, zcr=0;
        if (tid < 128) {
            zci = (cwi0*xi0 + cwi1*xi1 + cwi2*xi2 + cwi3*cur_i + cbi) * FACTOR_;
            zcf = (cwf0*xf0 + cwf1*xf1 + cwf2*xf2 + cwf3*cur_f + cbf) * FACTOR_;
            zcr = (cwr0*xr0 + cwr1*xr1 + cwr2*xr2 + cwr3*cur_r + cbr) * FACTOR_;
        }

        if ((s & (CHUNK_S - 1)) == (CHUNK_S - 1) && s + 1 < Ss) {
            volatile int* p = &g_done[(s + 1) >> 7];
            while (*p < TILES_PER_CHUNK) { __nanosleep(128); }
            __threadfence();
        }

        float ni = 0.f, nf = 0.f, nr = 0.f;
        if (tid < 128 && s + 1 < Ss) {
            const float* zs = zb + (size_t)(s + 1) * CHs;
            ni = zs[col];
            nf = zs[2048 + col];
            nr = zs[4096 + col];
        }

        unsigned long long ar0 = 0ULL, ar1 = 0ULL, af0 = 0ULL, af1 = 0ULL;
        {
            const ulonglong2* hp = (const ulonglong2*)(h_pair + d0);
#pragma unroll
            for (int j = 0; j < 16; j++) {
                ulonglong2 hv = hp[j];
                FMA2(ar0, hv.x, wr[2 * j]);
                FMA2(af0, hv.x, wf[2 * j]);
                FMA2(ar1, hv.y, wr[2 * j + 1]);
                FMA2(af1, hv.y, wf[2 * j + 1]);
            }
        }
        unsigned long long art, aft;
        ADD2(art, ar0, ar1);
        ADD2(aft, af0, af1);
        pr[q][c2] = art;
        pf[q][c2] = aft;
        __syncthreads();

        float ff = 0.f;
        if (tid < 128) {
            float rs = zcr + prf[tid] + prf[128 + tid] + prf[256 + tid] + prf[384 + tid];
            float fs = zcf + pff[tid] + pff[128 + tid] + pff[256 + tid] + pff[384 + tid];
            float r  = fast_sigmoid(rs);
            ff = fast_sigmoid(fs);
            float rh = r * hcur;
            rh_pair[tid] = pack2(rh, rh);
            sf[tid] = ff;
        }
        __syncthreads();

        unsigned long long ac0 = 0ULL, ac1 = 0ULL;
        {
            const ulonglong2* rp = (const ulonglong2*)(rh_pair + d0);
#pragma unroll
            for (int j = 0; j < 16; j++) {
                ulonglong2 hv = rp[j];
                FMA2(ac0, hv.x, wc[2 * j]);
                FMA2(ac1, hv.y, wc[2 * j + 1]);
            }
        }
        unsigned long long act;
        ADD2(act, ac0, ac1);
        pc[q][c2] = act;
        __syncthreads();

        if (tid < 128) {
            float cs = zci + pcf[tid] + pcf[128 + tid] + pcf[256 + tid] + pcf[384 + tid];
            float cd = fast_tanh(cs);
            float hn = fmaf(ff, hcur - cd, cd);
            hcur = hn;
            h_pair[tid] = pack2(hn, hn);
            __nv_bfloat16 bh = __float2bfloat16(hn);
            yhb[(size_t)s * STATEs] = bh;
            ylb[(size_t)s * STATEs] = __float2bfloat16(hn - __bfloat162float(bh));
            xi0 = xi1; xi1 = xi2; xi2 = cur_i; cur_i = ni;
            xf0 = xf1; xf1 = xf2; xf2 = cur_f; cur_f = nf;
            xr0 = xr1; xr1 = xr2; xr2 = cur_r; cur_r = nr;
        }
        __syncthreads();

        // publish y chunk (all 128 y-columns of this (b,hh) for the chunk done)
        if ((s & (CHUNK_S - 1)) == (CHUNK_S - 1)) {
            __threadfence();
            __syncthreads();
            if (tid == 0) atomicAdd(&g_ydone[b * N_CHUNKS + (s >> 7)], 1);
        }
    }
}

// ---------------- launch ----------------
extern "C" void kernel_launch(void* const* d_in, const int* in_sizes, int n_in,
                              void* d_out, int out_size)
{
    const float* x    = (const float*)d_in[0];
    const float* w_in = (const float*)d_in[1];
    const float* b_in = (const float*)d_in[2];
    const float* cw   = (const float*)d_in[3];
    const float* cb   = (const float*)d_in[4];
    const float* swt  = (const float*)d_in[5];
    const float* wout = (const float*)d_in[6];
    float* out = (float*)d_out;

    float* zp;
    cudaGetSymbolAddress((void**)&zp, g_z);
    __nv_bfloat16 *xh, *xl, *wh, *wl, *yh, *yl, *oh, *ol;
    cudaGetSymbolAddress((void**)&xh, g_xhi);
    cudaGetSymbolAddress((void**)&xl, g_xlo);
    cudaGetSymbolAddress((void**)&wh, g_whi);
    cudaGetSymbolAddress((void**)&wl, g_wlo);
    cudaGetSymbolAddress((void**)&yh, g_yhi);
    cudaGetSymbolAddress((void**)&yl, g_ylo);
    cudaGetSymbolAddress((void**)&oh, g_ohi);
    cudaGetSymbolAddress((void**)&ol, g_olo);

    // splits + flag reset
    {
        size_t nx = (size_t)Bb * Ss * INs;
        split_bf16<<<(int)(nx / 1024), 256>>>(x, xh, xl, nx);
        size_t nw = (size_t)CHs * INs;
        split_bf16<<<(int)(nw / 1024), 256>>>(w_in, wh, wl, nw);
        size_t no = (size_t)OUTs * STATEs;
        split_bf16<<<(int)(no / 1024), 256>>>(wout, oh, ol, no);
        zero_done<<<1, 128>>>();
    }

    // fused GEMM1 + conv + scan + GEMM2
    {
        cudaFuncSetAttribute(fused_all,
                             cudaFuncAttributeMaxDynamicSharedMemorySize,
                             FUSED_SMEM);
        fused_all<<<N_SCAN_CTAS + N_WORKERS, 256, FUSED_SMEM>>>(
            xh, xl, wh, wl, b_in, zp, swt, cw, cb, yh, yl, oh, ol, out);
    }
}